// round 2
// baseline (speedup 1.0000x reference)
#include <cuda_runtime.h>

#define N_NODES 50000
#define N_EDGES 800000
#define D_FEAT  64
#define ROWS_PER_BLOCK 8   // 8 warps/block, one row per warp
#define CHUNK 8            // per-warp gather pipeline depth

// out[r][:] = sum_{e: row_idx[e]==r} vals[e] * embeds[col_idx[e]][:]
// row_idx sorted ascending. Warp-per-row, 32 lanes x float2 = 64 dims.
// Inner loop batches CHUNK independent gathers to hide L2-hit latency.
__global__ __launch_bounds__(ROWS_PER_BLOCK * 32)
void gcn_spmm_kernel(const int* __restrict__ row_idx,
                     const int* __restrict__ col_idx,
                     const float* __restrict__ vals,
                     const float* __restrict__ embeds,
                     float* __restrict__ out) {
    __shared__ int s_ptr[ROWS_PER_BLOCK + 1];

    const int tid  = threadIdx.x;
    const int base = blockIdx.x * ROWS_PER_BLOCK;

    // lower_bound(row_idx, base + t) for t = 0..8
    if (tid <= ROWS_PER_BLOCK) {
        const int target = base + tid;
        int lo = 0, hi = N_EDGES;
        while (lo < hi) {
            const int mid = (lo + hi) >> 1;
            if (__ldg(row_idx + mid) < target) lo = mid + 1; else hi = mid;
        }
        s_ptr[tid] = lo;
    }
    __syncthreads();

    const int wid  = tid >> 5;
    const int lane = tid & 31;
    const int row  = base + wid;

    const int start = s_ptr[wid];
    const int end   = s_ptr[wid + 1];

    const float2* __restrict__ emb2 = reinterpret_cast<const float2*>(embeds);

    float2 acc = make_float2(0.0f, 0.0f);

    for (int e = start; e < end; e += CHUNK) {
        int   c[CHUNK];
        float v[CHUNK];
        // Batch the metadata loads (uniform addresses across the warp ->
        // broadcast; contiguous stream -> L1 hits after first line).
        #pragma unroll
        for (int i = 0; i < CHUNK; i++) {
            if (e + i < end) {              // uniform branch -> predication
                c[i] = __ldg(col_idx + e + i);
                v[i] = __ldg(vals + e + i);
            } else {
                c[i] = 0;
                v[i] = 0.0f;
            }
        }
        // Issue all CHUNK gathers before consuming any -> MLP = CHUNK.
        float2 x[CHUNK];
        #pragma unroll
        for (int i = 0; i < CHUNK; i++) {
            if (e + i < end)
                x[i] = __ldg(emb2 + (size_t)c[i] * 32 + lane);
        }
        #pragma unroll
        for (int i = 0; i < CHUNK; i++) {
            if (e + i < end) {
                acc.x = fmaf(v[i], x[i].x, acc.x);
                acc.y = fmaf(v[i], x[i].y, acc.y);
            }
        }
    }

    // Coalesced 256B row store; empty rows write zeros over the poison.
    reinterpret_cast<float2*>(out)[(size_t)row * 32 + lane] = acc;
}

extern "C" void kernel_launch(void* const* d_in, const int* in_sizes, int n_in,
                              void* d_out, int out_size) {
    const int*   row_idx = (const int*)  d_in[0];
    const int*   col_idx = (const int*)  d_in[1];
    const float* vals    = (const float*)d_in[2];
    const float* embeds  = (const float*)d_in[3];
    float*       out     = (float*)d_out;

    const int blocks = N_NODES / ROWS_PER_BLOCK;   // 6250
    gcn_spmm_kernel<<<blocks, ROWS_PER_BLOCK * 32>>>(row_idx, col_idx, vals,
                                                     embeds, out);
}

// round 3
// speedup vs baseline: 1.8980x; 1.8980x over previous
#include <cuda_runtime.h>

#define N_NODES 50000
#define N_EDGES 800000
#define D_FEAT  64
#define ROWS_PER_BLOCK 8
#define CHUNK 8

// Precomputed CSR row pointers (lower bounds into sorted row_idx).
__device__ int g_row_ptr[N_NODES + 1];

// Kernel A: one thread per boundary target, independent binary searches.
// 50001 threads; dependent-load chains fully overlapped across ~1563 warps.
__global__ __launch_bounds__(256)
void build_row_ptr_kernel(const int* __restrict__ row_idx) {
    const int t = blockIdx.x * blockDim.x + threadIdx.x;
    if (t > N_NODES) return;
    int lo = 0, hi = N_EDGES;
    while (lo < hi) {
        const int mid = (lo + hi) >> 1;
        if (__ldg(row_idx + mid) < t) lo = mid + 1; else hi = mid;
    }
    g_row_ptr[t] = lo;
}

// Kernel B: warp-per-row SpMM. 32 lanes x float2 = 64 dims.
// Main loop: CHUNK unguarded, back-to-back gathers (true MLP=CHUNK).
__global__ __launch_bounds__(ROWS_PER_BLOCK * 32)
void gcn_spmm_kernel(const int* __restrict__ col_idx,
                     const float* __restrict__ vals,
                     const float* __restrict__ embeds,
                     float* __restrict__ out) {
    const int tid  = threadIdx.x;
    const int wid  = tid >> 5;
    const int lane = tid & 31;
    const int row  = blockIdx.x * ROWS_PER_BLOCK + wid;

    const int start = __ldg(&g_row_ptr[row]);
    const int end   = __ldg(&g_row_ptr[row + 1]);

    const float2* __restrict__ emb2 = reinterpret_cast<const float2*>(embeds);

    float2 acc = make_float2(0.0f, 0.0f);

    int e = start;
    // Clean, unguarded chunks: 8 independent gathers in flight per warp.
    for (; e + CHUNK <= end; e += CHUNK) {
        int   c[CHUNK];
        float v[CHUNK];
        #pragma unroll
        for (int i = 0; i < CHUNK; i++) {
            c[i] = __ldg(col_idx + e + i);
            v[i] = __ldg(vals + e + i);
        }
        float2 x[CHUNK];
        #pragma unroll
        for (int i = 0; i < CHUNK; i++)
            x[i] = __ldg(emb2 + (size_t)c[i] * 32 + lane);
        #pragma unroll
        for (int i = 0; i < CHUNK; i++) {
            acc.x = fmaf(v[i], x[i].x, acc.x);
            acc.y = fmaf(v[i], x[i].y, acc.y);
        }
    }
    // Tail (< CHUNK edges), simple serial loop.
    for (; e < end; e++) {
        const int   c0 = __ldg(col_idx + e);
        const float v0 = __ldg(vals + e);
        const float2 x0 = __ldg(emb2 + (size_t)c0 * 32 + lane);
        acc.x = fmaf(v0, x0.x, acc.x);
        acc.y = fmaf(v0, x0.y, acc.y);
    }

    // Coalesced 256B row store; empty rows write zeros over the poison.
    reinterpret_cast<float2*>(out)[(size_t)row * 32 + lane] = acc;
}

extern "C" void kernel_launch(void* const* d_in, const int* in_sizes, int n_in,
                              void* d_out, int out_size) {
    const int*   row_idx = (const int*)  d_in[0];
    const int*   col_idx = (const int*)  d_in[1];
    const float* vals    = (const float*)d_in[2];
    const float* embeds  = (const float*)d_in[3];
    float*       out     = (float*)d_out;

    build_row_ptr_kernel<<<(N_NODES + 1 + 255) / 256, 256>>>(row_idx);

    const int blocks = N_NODES / ROWS_PER_BLOCK;   // 6250
    gcn_spmm_kernel<<<blocks, ROWS_PER_BLOCK * 32>>>(col_idx, vals, embeds, out);
}